// round 3
// baseline (speedup 1.0000x reference)
#include <cuda_runtime.h>

// ---------------------------------------------------------------------------
// Shapes fixed by the dataset: N=131072 nodes, S=32, E=2M edges, B=4096
// ---------------------------------------------------------------------------
#define MAXN 131072
#define MAXB 4096

// Scratch (static device globals)
__device__ float g_wdi[3][512];       // per-conv: (W1a - W1b), [F x 16]
__device__ float g_wdj[3][512];       // per-conv: W1b,         [F x 16]
__device__ float g_awt[256 * 64];     // aW transposed to [256, 64]
__device__ float g_pij[MAXN * 32];    // per-node [pi(16)+b1 | pj(16)]
__device__ float g_h16[MAXN * 16];    // aggregated relu(hidden) per node
__device__ float g_hacc[MAXN * 32];   // conv output (pre-BN)
__device__ float g_h[MAXN * 32];      // final activations (dense input)
__device__ int   g_deg[MAXN];         // in-degree per node
__device__ float g_stats[64];         // per-channel sum / sumsq
__device__ float g_t1[MAXB * 256];
__device__ float g_t2[MAXB * 256];
__device__ float g_val[MAXB];
__device__ float g_adv[MAXB * 64];

// ---------------------------------------------------------------------------
// prep: fold EdgeConv concat into two weight mats; transpose aW
// ---------------------------------------------------------------------------
__global__ void prep_kernel(const float* __restrict__ c1W1,
                            const float* __restrict__ c2W1,
                            const float* __restrict__ c3W1,
                            const float* __restrict__ aW) {
    int t = blockIdx.x * blockDim.x + threadIdx.x;
    if (t < 32) {
        int k = t >> 4, j = t & 15;
        g_wdi[0][t] = c1W1[k * 16 + j] - c1W1[(2 + k) * 16 + j];
        g_wdj[0][t] = c1W1[(2 + k) * 16 + j];
    }
    if (t < 512) {
        int k = t >> 4, j = t & 15;
        g_wdi[1][t] = c2W1[k * 16 + j] - c2W1[(32 + k) * 16 + j];
        g_wdj[1][t] = c2W1[(32 + k) * 16 + j];
        g_wdi[2][t] = c3W1[k * 16 + j] - c3W1[(32 + k) * 16 + j];
        g_wdj[2][t] = c3W1[(32 + k) * 16 + j];
    }
    for (int i = t; i < 256 * 64; i += blockDim.x * gridDim.x) {
        int f = i >> 6, col = i & 63;
        g_awt[i] = aW[(col >> 1) * 512 + f * 2 + (col & 1)];
    }
}

// in-degree per node (one pass, reused by all 3 convs)
__global__ void deg_kernel(const int* __restrict__ dst, int E) {
    int e = blockIdx.x * blockDim.x + threadIdx.x;
    if (e < E) atomicAdd(&g_deg[dst[e]], 1);
}

// conv1 pi/pj from raw x (F=2); b1 folded into pi
__global__ void prep1_kernel(const float* __restrict__ x,
                             const float* __restrict__ b1v, int N) {
    __shared__ float sWd[32], sWb[32], sB1[16];
    if (threadIdx.x < 32) {
        sWd[threadIdx.x] = g_wdi[0][threadIdx.x];
        sWb[threadIdx.x] = g_wdj[0][threadIdx.x];
    }
    if (threadIdx.x < 16) sB1[threadIdx.x] = b1v[threadIdx.x];
    __syncthreads();
    int n = blockIdx.x * blockDim.x + threadIdx.x;
    if (n >= N) return;
    float2 xv = reinterpret_cast<const float2*>(x)[n];
    float out[32];
#pragma unroll
    for (int j = 0; j < 16; j++) {
        out[j]      = sB1[j] + fmaf(xv.x, sWd[j], xv.y * sWd[16 + j]);
        out[16 + j] = fmaf(xv.x, sWb[j], xv.y * sWb[16 + j]);
    }
    float4* o = reinterpret_cast<float4*>(g_pij + (size_t)n * 32);
#pragma unroll
    for (int q = 0; q < 8; q++)
        o[q] = make_float4(out[q * 4], out[q * 4 + 1], out[q * 4 + 2], out[q * 4 + 3]);
}

// ---------------------------------------------------------------------------
// edge scatter, 4 lanes per edge (lane q handles 16B quarter):
//   h = relu(pi'[dst] + pj[src]); red.add.v4 into g_h16[dst]
// Consecutive lanes of an edge hit contiguous 16B chunks of the same 128B
// line -> ~8 L1 wavefronts per warp-LDG instead of 32.
// ---------------------------------------------------------------------------
__global__ void edge_scatter_kernel(const int* __restrict__ src,
                                    const int* __restrict__ dst, int E) {
    int t = blockIdx.x * blockDim.x + threadIdx.x;
    int e = t >> 2;
    int q = t & 3;
    if (e >= E) return;
    int s = __ldg(src + e);
    int d = __ldg(dst + e);
    float4 u = *reinterpret_cast<const float4*>(g_pij + (size_t)d * 32 + q * 4);
    float4 v = *reinterpret_cast<const float4*>(g_pij + (size_t)s * 32 + 16 + q * 4);
    float h0 = fmaxf(u.x + v.x, 0.0f);
    float h1 = fmaxf(u.y + v.y, 0.0f);
    float h2 = fmaxf(u.z + v.z, 0.0f);
    float h3 = fmaxf(u.w + v.w, 0.0f);
    asm volatile("red.global.add.v4.f32 [%0], {%1, %2, %3, %4};" ::
                     "l"(g_h16 + (size_t)d * 16 + q * 4),
                 "f"(h0), "f"(h1), "f"(h2), "f"(h3)
                 : "memory");
}

// ---------------------------------------------------------------------------
// node post: o = H16agg @ W2 + deg*b2; write g_hacc; fused BN stats
// Launch with grid*block == N exactly (N multiple of 256).
// ---------------------------------------------------------------------------
__global__ void node_post_kernel(const float* __restrict__ W2,
                                 const float* __restrict__ b2v, int N) {
    __shared__ float sW2[512];
    __shared__ float sB2[32];
    __shared__ float ssum[8][32];
    __shared__ float ssq[8][32];
    for (int i = threadIdx.x; i < 512; i += blockDim.x) sW2[i] = W2[i];
    if (threadIdx.x < 32) sB2[threadIdx.x] = b2v[threadIdx.x];
    __syncthreads();

    int n = blockIdx.x * blockDim.x + threadIdx.x;
    int lane = threadIdx.x & 31;
    int warp = threadIdx.x >> 5;

    float hv[16];
    const float4* hp = reinterpret_cast<const float4*>(g_h16 + (size_t)n * 16);
#pragma unroll
    for (int q = 0; q < 4; q++) {
        float4 v = hp[q];
        hv[q * 4 + 0] = v.x; hv[q * 4 + 1] = v.y;
        hv[q * 4 + 2] = v.z; hv[q * 4 + 3] = v.w;
    }
    float dg = (float)g_deg[n];
    float o[32];
#pragma unroll
    for (int j = 0; j < 32; j++) o[j] = dg * sB2[j];
#pragma unroll
    for (int k = 0; k < 16; k++) {
        float v = hv[k];
#pragma unroll
        for (int j = 0; j < 32; j++) o[j] = fmaf(v, sW2[k * 32 + j], o[j]);
    }
    float4* op = reinterpret_cast<float4*>(g_hacc + (size_t)n * 32);
#pragma unroll
    for (int q = 0; q < 8; q++)
        op[q] = make_float4(o[q * 4], o[q * 4 + 1], o[q * 4 + 2], o[q * 4 + 3]);

    // fused BN stats: warp butterfly per channel, then block + global reduce
#pragma unroll
    for (int j = 0; j < 32; j++) {
        float v = o[j];
        float v2 = v * v;
#pragma unroll
        for (int off = 16; off; off >>= 1) {
            v += __shfl_xor_sync(0xffffffffu, v, off);
            v2 += __shfl_xor_sync(0xffffffffu, v2, off);
        }
        if (lane == 0) { ssum[warp][j] = v; ssq[warp][j] = v2; }
    }
    __syncthreads();
    if (warp == 0) {
        float a = 0.0f, b = 0.0f;
#pragma unroll
        for (int w = 0; w < 8; w++) { a += ssum[w][lane]; b += ssq[w][lane]; }
        atomicAdd(&g_stats[lane], a);
        atomicAdd(&g_stats[32 + lane], b);
    }
}

// ---------------------------------------------------------------------------
// BN apply + ReLU, fused with next conv's pi/pj precompute (or final write).
// Next conv's b1 folded into pi.
// ---------------------------------------------------------------------------
template <bool FINAL>
__global__ void bn_prep_kernel(const float* __restrict__ gamma,
                               const float* __restrict__ beta,
                               const float* __restrict__ b1next, int wi, int N) {
    __shared__ float sc[32], sh[32];
    __shared__ float sWd[512], sWb[512], sB1[16];
    if (threadIdx.x < 32) {
        int c = threadIdx.x;
        float invn = 1.0f / (float)N;
        float mu = g_stats[c] * invn;
        float var = g_stats[32 + c] * invn - mu * mu;
        float s = rsqrtf(var + 1e-5f) * gamma[c];
        sc[c] = s;
        sh[c] = beta[c] - mu * s;
    }
    if (!FINAL) {
        for (int i = threadIdx.x; i < 512; i += blockDim.x) {
            sWd[i] = g_wdi[wi][i];
            sWb[i] = g_wdj[wi][i];
        }
        if (threadIdx.x >= 32 && threadIdx.x < 48) sB1[threadIdx.x - 32] = b1next[threadIdx.x - 32];
    }
    __syncthreads();
    int n = blockIdx.x * blockDim.x + threadIdx.x;
    if (n >= N) return;

    float hn[32];
    const float4* ip = reinterpret_cast<const float4*>(g_hacc + (size_t)n * 32);
#pragma unroll
    for (int q = 0; q < 8; q++) {
        float4 v = ip[q];
        hn[q * 4 + 0] = fmaxf(fmaf(v.x, sc[q * 4 + 0], sh[q * 4 + 0]), 0.0f);
        hn[q * 4 + 1] = fmaxf(fmaf(v.y, sc[q * 4 + 1], sh[q * 4 + 1]), 0.0f);
        hn[q * 4 + 2] = fmaxf(fmaf(v.z, sc[q * 4 + 2], sh[q * 4 + 2]), 0.0f);
        hn[q * 4 + 3] = fmaxf(fmaf(v.w, sc[q * 4 + 3], sh[q * 4 + 3]), 0.0f);
    }
    if (FINAL) {
        float4* op = reinterpret_cast<float4*>(g_h + (size_t)n * 32);
#pragma unroll
        for (int q = 0; q < 8; q++)
            op[q] = make_float4(hn[q * 4], hn[q * 4 + 1], hn[q * 4 + 2], hn[q * 4 + 3]);
    } else {
        float pi[16], pj[16];
#pragma unroll
        for (int j = 0; j < 16; j++) { pi[j] = sB1[j]; pj[j] = 0.0f; }
#pragma unroll
        for (int k = 0; k < 32; k++) {
            float v = hn[k];
#pragma unroll
            for (int j = 0; j < 16; j++) {
                pi[j] = fmaf(v, sWd[k * 16 + j], pi[j]);
                pj[j] = fmaf(v, sWb[k * 16 + j], pj[j]);
            }
        }
        float4* op = reinterpret_cast<float4*>(g_pij + (size_t)n * 32);
#pragma unroll
        for (int q = 0; q < 4; q++) {
            op[q] = make_float4(pi[q * 4], pi[q * 4 + 1], pi[q * 4 + 2], pi[q * 4 + 3]);
            op[4 + q] = make_float4(pj[q * 4], pj[q * 4 + 1], pj[q * 4 + 2], pj[q * 4 + 3]);
        }
    }
}

// ---------------------------------------------------------------------------
// Tiled fp32 GEMM: C[M,N] = act(A @ B + bias), 64x64 tile, BK=16
// ---------------------------------------------------------------------------
template <bool RELU>
__global__ void gemm_bias_kernel(const float* __restrict__ A,
                                 const float* __restrict__ Bm,
                                 const float* __restrict__ bias,
                                 float* __restrict__ C, int M, int N, int K) {
    const int BM = 64, BN = 64, BK = 16;
    __shared__ float As[BK][BM + 1];
    __shared__ float Bs[BK][BN];
    int tx = threadIdx.x & 15;
    int ty = threadIdx.x >> 4;
    int bm = blockIdx.y * BM;
    int bn = blockIdx.x * BN;

    float acc[4][4];
#pragma unroll
    for (int u = 0; u < 4; u++)
#pragma unroll
        for (int v = 0; v < 4; v++) acc[u][v] = 0.0f;

    for (int k0 = 0; k0 < K; k0 += BK) {
        for (int i = threadIdx.x; i < BM * BK; i += 256) {
            int r = i / BK, c = i % BK;
            As[c][r] = A[(size_t)(bm + r) * K + k0 + c];
        }
        for (int i = threadIdx.x; i < BK * BN; i += 256) {
            int r = i / BN, c = i % BN;
            Bs[r][c] = Bm[(size_t)(k0 + r) * N + bn + c];
        }
        __syncthreads();
#pragma unroll
        for (int k = 0; k < BK; k++) {
            float a[4], b[4];
#pragma unroll
            for (int u = 0; u < 4; u++) a[u] = As[k][ty * 4 + u];
            float4 bv = *reinterpret_cast<const float4*>(&Bs[k][tx * 4]);
            b[0] = bv.x; b[1] = bv.y; b[2] = bv.z; b[3] = bv.w;
#pragma unroll
            for (int u = 0; u < 4; u++)
#pragma unroll
                for (int v = 0; v < 4; v++) acc[u][v] = fmaf(a[u], b[v], acc[u][v]);
        }
        __syncthreads();
    }
#pragma unroll
    for (int u = 0; u < 4; u++) {
        int row = bm + ty * 4 + u;
#pragma unroll
        for (int v = 0; v < 4; v++) {
            int col = bn + tx * 4 + v;
            float r = acc[u][v] + bias[col];
            if (RELU) r = fmaxf(r, 0.0f);
            C[(size_t)row * N + col] = r;
        }
    }
}

__global__ void value_kernel(const float* __restrict__ X,
                             const float* __restrict__ vW,
                             const float* __restrict__ vb, int B) {
    int gwarp = (blockIdx.x * blockDim.x + threadIdx.x) >> 5;
    int lane = threadIdx.x & 31;
    int nwarps = (gridDim.x * blockDim.x) >> 5;
    for (int b = gwarp; b < B; b += nwarps) {
        const float* row = X + (size_t)b * 256;
        float s = 0.0f;
#pragma unroll
        for (int f = lane; f < 256; f += 32) s = fmaf(row[f], vW[f], s);
#pragma unroll
        for (int o = 16; o; o >>= 1) s += __shfl_xor_sync(0xffffffffu, s, o);
        if (lane == 0) g_val[b] = s + vb[0];
    }
}

__global__ void q_kernel(float* __restrict__ q, int B) {
    int i = blockIdx.x * blockDim.x + threadIdx.x;
    if (i >= B * 64) return;
    int b = i >> 6;
    float a0 = g_adv[i];
    float a1 = g_adv[i ^ 1];
    q[i] = g_val[b] + 0.5f * (a0 - a1);
}

// ---------------------------------------------------------------------------
extern "C" void kernel_launch(void* const* d_in, const int* in_sizes, int n_in,
                              void* d_out, int out_size) {
    const float* x    = (const float*)d_in[0];
    const int*   ei   = (const int*)d_in[1];
    const float* c1W1 = (const float*)d_in[2];
    const float* c1b1 = (const float*)d_in[3];
    const float* c1W2 = (const float*)d_in[4];
    const float* c1b2 = (const float*)d_in[5];
    const float* c2W1 = (const float*)d_in[6];
    const float* c2b1 = (const float*)d_in[7];
    const float* c2W2 = (const float*)d_in[8];
    const float* c2b2 = (const float*)d_in[9];
    const float* c3W1 = (const float*)d_in[10];
    const float* c3b1 = (const float*)d_in[11];
    const float* c3W2 = (const float*)d_in[12];
    const float* c3b2 = (const float*)d_in[13];
    const float* bn_g = (const float*)d_in[14];
    const float* bn_b = (const float*)d_in[15];
    const float* mW1  = (const float*)d_in[16];
    const float* mb1  = (const float*)d_in[17];
    const float* mW2  = (const float*)d_in[18];
    const float* mb2  = (const float*)d_in[19];
    const float* mW3  = (const float*)d_in[20];
    const float* mb3  = (const float*)d_in[21];
    const float* vW   = (const float*)d_in[22];
    const float* vb   = (const float*)d_in[23];
    const float* aW   = (const float*)d_in[24];
    const float* ab   = (const float*)d_in[25];

    int N = in_sizes[0] / 2;
    int E = in_sizes[1] / 2;
    int B = N / 32;
    const int* src = ei;
    const int* dstp = ei + E;

    float *h16, *h, *stats, *t1, *t2, *adv, *awt;
    int* deg;
    cudaGetSymbolAddress((void**)&h16, g_h16);
    cudaGetSymbolAddress((void**)&h, g_h);
    cudaGetSymbolAddress((void**)&stats, g_stats);
    cudaGetSymbolAddress((void**)&t1, g_t1);
    cudaGetSymbolAddress((void**)&t2, g_t2);
    cudaGetSymbolAddress((void**)&adv, g_adv);
    cudaGetSymbolAddress((void**)&awt, g_awt);
    cudaGetSymbolAddress((void**)&deg, g_deg);

    const int TPB = 256;
    int nblocks = N / TPB;              // N is a multiple of 256
    int eblocks = (E + TPB - 1) / TPB;
    int e4blocks = ((size_t)E * 4 + TPB - 1) / TPB;
    size_t h16bytes = (size_t)N * 16 * sizeof(float);

    prep_kernel<<<64, 256>>>(c1W1, c2W1, c3W1, aW);
    cudaMemsetAsync(deg, 0, (size_t)N * sizeof(int), 0);
    deg_kernel<<<eblocks, TPB>>>(dstp, E);
    prep1_kernel<<<nblocks, TPB>>>(x, c1b1, N);

    const float* W2s[3] = {c1W2, c2W2, c3W2};
    const float* b2s[3] = {c1b2, c2b2, c3b2};
    const float* b1next[3] = {c2b1, c3b1, c3b1};

    for (int c = 0; c < 3; c++) {
        cudaMemsetAsync(h16, 0, h16bytes, 0);
        cudaMemsetAsync(stats, 0, 64 * sizeof(float), 0);
        edge_scatter_kernel<<<e4blocks, TPB>>>(src, dstp, E);
        node_post_kernel<<<nblocks, TPB>>>(W2s[c], b2s[c], N);
        if (c < 2)
            bn_prep_kernel<false><<<nblocks, TPB>>>(bn_g + c * 32, bn_b + c * 32,
                                                    b1next[c], c + 1, N);
        else
            bn_prep_kernel<true><<<nblocks, TPB>>>(bn_g + 64, bn_b + 64, c3b1, 0, N);
    }

    // ---- dense head: g_h is [B, 1024] row-major ----
    dim3 g1(256 / 64, B / 64);
    gemm_bias_kernel<true><<<g1, 256>>>(h, mW1, mb1, t1, B, 256, 1024);
    gemm_bias_kernel<true><<<g1, 256>>>(t1, mW2, mb2, t2, B, 256, 256);
    gemm_bias_kernel<true><<<g1, 256>>>(t2, mW3, mb3, t1, B, 256, 256);

    value_kernel<<<64, 256>>>(t1, vW, vb, B);
    dim3 g2(1, B / 64);
    gemm_bias_kernel<false><<<g2, 256>>>(t1, awt, ab, adv, B, 64, 256);
    q_kernel<<<(B * 64 + 255) / 256, 256>>>((float*)d_out, B);
}

// round 4
// speedup vs baseline: 1.5164x; 1.5164x over previous
#include <cuda_runtime.h>

// ---------------------------------------------------------------------------
// Shapes fixed by the dataset: N=131072 nodes, S=32, E=2M edges, B=4096
// ---------------------------------------------------------------------------
#define MAXN 131072
#define MAXE (2 * 1024 * 1024)
#define MAXB 4096
#define NBLK 512                      // N / 256

// Scratch (static device globals)
__device__ float g_wdi[3][512];       // per-conv: (W1a - W1b), [F x 16]
__device__ float g_wdj[3][512];       // per-conv: W1b,         [F x 16]
__device__ float g_awt[256 * 64];     // aW transposed to [256, 64]
__device__ float g_pij[MAXN * 32];    // per-node [pi(16)+b1 | pj(16)]
__device__ float g_hacc[MAXN * 32];   // conv output (pre-BN)
__device__ float g_h[MAXN * 32];      // final activations (dense input)
__device__ int   g_deg[MAXN];         // in-degree per node
__device__ int   g_rowptr[MAXN];      // CSR row start
__device__ int   g_cursor[MAXN];      // fill cursors
__device__ int   g_col[MAXE];         // src ids grouped by dst
__device__ int   g_bsums[NBLK];       // scan scratch
__device__ float g_stats[64];         // per-channel sum / sumsq
__device__ float g_t1[MAXB * 256];
__device__ float g_t2[MAXB * 256];
__device__ float g_val[MAXB];
__device__ float g_adv[MAXB * 64];

// ---------------------------------------------------------------------------
// prep: fold EdgeConv concat into two weight mats; transpose aW
// ---------------------------------------------------------------------------
__global__ void prep_kernel(const float* __restrict__ c1W1,
                            const float* __restrict__ c2W1,
                            const float* __restrict__ c3W1,
                            const float* __restrict__ aW) {
    int t = blockIdx.x * blockDim.x + threadIdx.x;
    if (t < 32) {
        int k = t >> 4, j = t & 15;
        g_wdi[0][t] = c1W1[k * 16 + j] - c1W1[(2 + k) * 16 + j];
        g_wdj[0][t] = c1W1[(2 + k) * 16 + j];
    }
    if (t < 512) {
        int k = t >> 4, j = t & 15;
        g_wdi[1][t] = c2W1[k * 16 + j] - c2W1[(32 + k) * 16 + j];
        g_wdj[1][t] = c2W1[(32 + k) * 16 + j];
        g_wdi[2][t] = c3W1[k * 16 + j] - c3W1[(32 + k) * 16 + j];
        g_wdj[2][t] = c3W1[(32 + k) * 16 + j];
    }
    for (int i = t; i < 256 * 64; i += blockDim.x * gridDim.x) {
        int f = i >> 6, col = i & 63;
        g_awt[i] = aW[(col >> 1) * 512 + f * 2 + (col & 1)];
    }
}

// ---------------------------------------------------------------------------
// CSR build: degree -> two-level exclusive scan -> cursor fill
// ---------------------------------------------------------------------------
__global__ void deg_kernel(const int* __restrict__ dst, int E) {
    int e = blockIdx.x * blockDim.x + threadIdx.x;
    if (e < E) atomicAdd(&g_deg[dst[e]], 1);
}

__global__ void blocksum_kernel() {  // grid NBLK, block 256
    int v = g_deg[blockIdx.x * 256 + threadIdx.x];
#pragma unroll
    for (int o = 16; o; o >>= 1) v += __shfl_xor_sync(0xffffffffu, v, o);
    __shared__ int ws[8];
    if ((threadIdx.x & 31) == 0) ws[threadIdx.x >> 5] = v;
    __syncthreads();
    if (threadIdx.x == 0) {
        int s = 0;
#pragma unroll
        for (int w = 0; w < 8; w++) s += ws[w];
        g_bsums[blockIdx.x] = s;
    }
}

__global__ void scanblocks_kernel(int nb) {  // 1 block, NBLK threads
    __shared__ int sh[NBLK];
    int t = threadIdx.x;
    sh[t] = (t < nb) ? g_bsums[t] : 0;
    __syncthreads();
    for (int o = 1; o < NBLK; o <<= 1) {
        int v = (t >= o) ? sh[t - o] : 0;
        __syncthreads();
        sh[t] += v;
        __syncthreads();
    }
    g_bsums[t] = (t == 0) ? 0 : sh[t - 1];  // exclusive
}

__global__ void rowptr_kernel() {  // grid NBLK, block 256
    __shared__ int sh[256];
    int t = threadIdx.x;
    int n = blockIdx.x * 256 + t;
    int d = g_deg[n];
    sh[t] = d;
    __syncthreads();
    for (int o = 1; o < 256; o <<= 1) {
        int v = (t >= o) ? sh[t - o] : 0;
        __syncthreads();
        sh[t] += v;
        __syncthreads();
    }
    int start = g_bsums[blockIdx.x] + sh[t] - d;
    g_rowptr[n] = start;
    g_cursor[n] = start;
}

__global__ void fill_kernel(const int* __restrict__ src,
                            const int* __restrict__ dst, int E) {
    int e = blockIdx.x * blockDim.x + threadIdx.x;
    if (e < E) {
        int p = atomicAdd(&g_cursor[dst[e]], 1);
        g_col[p] = src[e];
    }
}

// conv1 pi/pj from raw x (F=2); b1 folded into pi
__global__ void prep1_kernel(const float* __restrict__ x,
                             const float* __restrict__ b1v, int N) {
    __shared__ float sWd[32], sWb[32], sB1[16];
    if (threadIdx.x < 32) {
        sWd[threadIdx.x] = g_wdi[0][threadIdx.x];
        sWb[threadIdx.x] = g_wdj[0][threadIdx.x];
    }
    if (threadIdx.x < 16) sB1[threadIdx.x] = b1v[threadIdx.x];
    __syncthreads();
    int n = blockIdx.x * blockDim.x + threadIdx.x;
    if (n >= N) return;
    float2 xv = reinterpret_cast<const float2*>(x)[n];
    float out[32];
#pragma unroll
    for (int j = 0; j < 16; j++) {
        out[j]      = sB1[j] + fmaf(xv.x, sWd[j], xv.y * sWd[16 + j]);
        out[16 + j] = fmaf(xv.x, sWb[j], xv.y * sWb[16 + j]);
    }
    float4* o = reinterpret_cast<float4*>(g_pij + (size_t)n * 32);
#pragma unroll
    for (int q = 0; q < 8; q++)
        o[q] = make_float4(out[q * 4], out[q * 4 + 1], out[q * 4 + 2], out[q * 4 + 3]);
}

// ---------------------------------------------------------------------------
// csr_conv: gather-only conv. 4 lanes per node, each lane owns a 16B quarter.
//   h16 = Sum_j relu(pi[n] + pj[col[j]])         (register accumulation)
//   o   = h16 @ W2 + deg*b2                      (shfl exchange, no smem trip)
//   g_hacc[n] = o ; fused BN stats
// Launch: grid = N/64, block 256.
// ---------------------------------------------------------------------------
__global__ void csr_conv_kernel(const float* __restrict__ W2,
                                const float* __restrict__ b2v, int N) {
    __shared__ float sW2[512];
    __shared__ float sB2[32];
    __shared__ float bsum[32], bsq[32];
    int t = threadIdx.x;
    for (int i = t; i < 512; i += 256) sW2[i] = W2[i];
    if (t < 32) {
        sB2[t] = b2v[t];
        bsum[t] = 0.0f;
        bsq[t] = 0.0f;
    }
    __syncthreads();

    int l = t >> 2;          // node within block (0..63)
    int q = t & 3;           // quarter (0..3)
    int n = blockIdx.x * 64 + l;

    float4 u = *reinterpret_cast<const float4*>(g_pij + (size_t)n * 32 + q * 4);
    int rp = g_rowptr[n];
    int dg = g_deg[n];

    float4 acc = make_float4(0.0f, 0.0f, 0.0f, 0.0f);
    for (int i = 0; i < dg; i++) {
        int s = __ldg(g_col + rp + i);
        float4 v = *reinterpret_cast<const float4*>(g_pij + (size_t)s * 32 + 16 + q * 4);
        acc.x += fmaxf(u.x + v.x, 0.0f);
        acc.y += fmaxf(u.y + v.y, 0.0f);
        acc.z += fmaxf(u.z + v.z, 0.0f);
        acc.w += fmaxf(u.w + v.w, 0.0f);
    }

    // exchange quarters within the 4-lane node group -> full h[16] per lane
    int lanebase = (t & 31) & ~3;
    float h[16];
#pragma unroll
    for (int k = 0; k < 16; k++) {
        float comp = (k & 3) == 0 ? acc.x : (k & 3) == 1 ? acc.y
                   : (k & 3) == 2 ? acc.z : acc.w;
        h[k] = __shfl_sync(0xffffffffu, comp, lanebase | (k >> 2), 32);
    }

    // o[8] for output channels j0..j0+7
    int j0 = q * 8;
    float dgf = (float)dg;
    float o[8];
#pragma unroll
    for (int j = 0; j < 8; j++) o[j] = dgf * sB2[j0 + j];
#pragma unroll
    for (int k = 0; k < 16; k++) {
        float hv = h[k];
#pragma unroll
        for (int j = 0; j < 8; j++) o[j] = fmaf(hv, sW2[k * 32 + j0 + j], o[j]);
    }
    float4* op = reinterpret_cast<float4*>(g_hacc + (size_t)n * 32 + j0);
    op[0] = make_float4(o[0], o[1], o[2], o[3]);
    op[1] = make_float4(o[4], o[5], o[6], o[7]);

    // BN stats: butterfly over the 8 nodes of this warp (lane strides 4,8,16)
#pragma unroll
    for (int j = 0; j < 8; j++) {
        float v = o[j];
        float v2 = v * v;
#pragma unroll
        for (int off = 4; off < 32; off <<= 1) {
            v += __shfl_xor_sync(0xffffffffu, v, off);
            v2 += __shfl_xor_sync(0xffffffffu, v2, off);
        }
        if ((t & 31) < 4) {
            atomicAdd(&bsum[j0 + j], v);
            atomicAdd(&bsq[j0 + j], v2);
        }
    }
    __syncthreads();
    if (t < 32)
        atomicAdd(&g_stats[t], bsum[t]);
    else if (t < 64)
        atomicAdd(&g_stats[t], bsq[t - 32]);
}

// ---------------------------------------------------------------------------
// BN apply + ReLU, fused with next conv's pi/pj precompute (or final write).
// ---------------------------------------------------------------------------
template <bool FINAL>
__global__ void bn_prep_kernel(const float* __restrict__ gamma,
                               const float* __restrict__ beta,
                               const float* __restrict__ b1next, int wi, int N) {
    __shared__ float sc[32], sh[32];
    __shared__ float sWd[512], sWb[512], sB1[16];
    if (threadIdx.x < 32) {
        int c = threadIdx.x;
        float invn = 1.0f / (float)N;
        float mu = g_stats[c] * invn;
        float var = g_stats[32 + c] * invn - mu * mu;
        float s = rsqrtf(var + 1e-5f) * gamma[c];
        sc[c] = s;
        sh[c] = beta[c] - mu * s;
    }
    if (!FINAL) {
        for (int i = threadIdx.x; i < 512; i += blockDim.x) {
            sWd[i] = g_wdi[wi][i];
            sWb[i] = g_wdj[wi][i];
        }
        if (threadIdx.x >= 32 && threadIdx.x < 48)
            sB1[threadIdx.x - 32] = b1next[threadIdx.x - 32];
    }
    __syncthreads();
    int n = blockIdx.x * blockDim.x + threadIdx.x;
    if (n >= N) return;

    float hn[32];
    const float4* ip = reinterpret_cast<const float4*>(g_hacc + (size_t)n * 32);
#pragma unroll
    for (int qq = 0; qq < 8; qq++) {
        float4 v = ip[qq];
        hn[qq * 4 + 0] = fmaxf(fmaf(v.x, sc[qq * 4 + 0], sh[qq * 4 + 0]), 0.0f);
        hn[qq * 4 + 1] = fmaxf(fmaf(v.y, sc[qq * 4 + 1], sh[qq * 4 + 1]), 0.0f);
        hn[qq * 4 + 2] = fmaxf(fmaf(v.z, sc[qq * 4 + 2], sh[qq * 4 + 2]), 0.0f);
        hn[qq * 4 + 3] = fmaxf(fmaf(v.w, sc[qq * 4 + 3], sh[qq * 4 + 3]), 0.0f);
    }
    if (FINAL) {
        float4* op = reinterpret_cast<float4*>(g_h + (size_t)n * 32);
#pragma unroll
        for (int qq = 0; qq < 8; qq++)
            op[qq] = make_float4(hn[qq * 4], hn[qq * 4 + 1], hn[qq * 4 + 2], hn[qq * 4 + 3]);
    } else {
        float pi[16], pj[16];
#pragma unroll
        for (int j = 0; j < 16; j++) { pi[j] = sB1[j]; pj[j] = 0.0f; }
#pragma unroll
        for (int k = 0; k < 32; k++) {
            float v = hn[k];
#pragma unroll
            for (int j = 0; j < 16; j++) {
                pi[j] = fmaf(v, sWd[k * 16 + j], pi[j]);
                pj[j] = fmaf(v, sWb[k * 16 + j], pj[j]);
            }
        }
        float4* op = reinterpret_cast<float4*>(g_pij + (size_t)n * 32);
#pragma unroll
        for (int qq = 0; qq < 4; qq++) {
            op[qq] = make_float4(pi[qq * 4], pi[qq * 4 + 1], pi[qq * 4 + 2], pi[qq * 4 + 3]);
            op[4 + qq] = make_float4(pj[qq * 4], pj[qq * 4 + 1], pj[qq * 4 + 2], pj[qq * 4 + 3]);
        }
    }
}

// ---------------------------------------------------------------------------
// Tiled fp32 GEMM: C[M,N] = act(A @ B + bias), 64x64 tile, BK=16
// ---------------------------------------------------------------------------
template <bool RELU>
__global__ void gemm_bias_kernel(const float* __restrict__ A,
                                 const float* __restrict__ Bm,
                                 const float* __restrict__ bias,
                                 float* __restrict__ C, int M, int N, int K) {
    const int BM = 64, BN = 64, BK = 16;
    __shared__ float As[BK][BM + 1];
    __shared__ float Bs[BK][BN];
    int tx = threadIdx.x & 15;
    int ty = threadIdx.x >> 4;
    int bm = blockIdx.y * BM;
    int bn = blockIdx.x * BN;

    float acc[4][4];
#pragma unroll
    for (int u = 0; u < 4; u++)
#pragma unroll
        for (int v = 0; v < 4; v++) acc[u][v] = 0.0f;

    for (int k0 = 0; k0 < K; k0 += BK) {
        for (int i = threadIdx.x; i < BM * BK; i += 256) {
            int r = i / BK, c = i % BK;
            As[c][r] = A[(size_t)(bm + r) * K + k0 + c];
        }
        for (int i = threadIdx.x; i < BK * BN; i += 256) {
            int r = i / BN, c = i % BN;
            Bs[r][c] = Bm[(size_t)(k0 + r) * N + bn + c];
        }
        __syncthreads();
#pragma unroll
        for (int k = 0; k < BK; k++) {
            float a[4], b[4];
#pragma unroll
            for (int u = 0; u < 4; u++) a[u] = As[k][ty * 4 + u];
            float4 bv = *reinterpret_cast<const float4*>(&Bs[k][tx * 4]);
            b[0] = bv.x; b[1] = bv.y; b[2] = bv.z; b[3] = bv.w;
#pragma unroll
            for (int u = 0; u < 4; u++)
#pragma unroll
                for (int v = 0; v < 4; v++) acc[u][v] = fmaf(a[u], b[v], acc[u][v]);
        }
        __syncthreads();
    }
#pragma unroll
    for (int u = 0; u < 4; u++) {
        int row = bm + ty * 4 + u;
#pragma unroll
        for (int v = 0; v < 4; v++) {
            int col = bn + tx * 4 + v;
            float r = acc[u][v] + bias[col];
            if (RELU) r = fmaxf(r, 0.0f);
            C[(size_t)row * N + col] = r;
        }
    }
}

__global__ void value_kernel(const float* __restrict__ X,
                             const float* __restrict__ vW,
                             const float* __restrict__ vb, int B) {
    int gwarp = (blockIdx.x * blockDim.x + threadIdx.x) >> 5;
    int lane = threadIdx.x & 31;
    int nwarps = (gridDim.x * blockDim.x) >> 5;
    for (int b = gwarp; b < B; b += nwarps) {
        const float* row = X + (size_t)b * 256;
        float s = 0.0f;
#pragma unroll
        for (int f = lane; f < 256; f += 32) s = fmaf(row[f], vW[f], s);
#pragma unroll
        for (int o = 16; o; o >>= 1) s += __shfl_xor_sync(0xffffffffu, s, o);
        if (lane == 0) g_val[b] = s + vb[0];
    }
}

__global__ void q_kernel(float* __restrict__ q, int B) {
    int i = blockIdx.x * blockDim.x + threadIdx.x;
    if (i >= B * 64) return;
    int b = i >> 6;
    float a0 = g_adv[i];
    float a1 = g_adv[i ^ 1];
    q[i] = g_val[b] + 0.5f * (a0 - a1);
}

// ---------------------------------------------------------------------------
extern "C" void kernel_launch(void* const* d_in, const int* in_sizes, int n_in,
                              void* d_out, int out_size) {
    const float* x    = (const float*)d_in[0];
    const int*   ei   = (const int*)d_in[1];
    const float* c1W1 = (const float*)d_in[2];
    const float* c1b1 = (const float*)d_in[3];
    const float* c1W2 = (const float*)d_in[4];
    const float* c1b2 = (const float*)d_in[5];
    const float* c2W1 = (const float*)d_in[6];
    const float* c2b1 = (const float*)d_in[7];
    const float* c2W2 = (const float*)d_in[8];
    const float* c2b2 = (const float*)d_in[9];
    const float* c3W1 = (const float*)d_in[10];
    const float* c3b1 = (const float*)d_in[11];
    const float* c3W2 = (const float*)d_in[12];
    const float* c3b2 = (const float*)d_in[13];
    const float* bn_g = (const float*)d_in[14];
    const float* bn_b = (const float*)d_in[15];
    const float* mW1  = (const float*)d_in[16];
    const float* mb1  = (const float*)d_in[17];
    const float* mW2  = (const float*)d_in[18];
    const float* mb2  = (const float*)d_in[19];
    const float* mW3  = (const float*)d_in[20];
    const float* mb3  = (const float*)d_in[21];
    const float* vW   = (const float*)d_in[22];
    const float* vb   = (const float*)d_in[23];
    const float* aW   = (const float*)d_in[24];
    const float* ab   = (const float*)d_in[25];

    int N = in_sizes[0] / 2;
    int E = in_sizes[1] / 2;
    int B = N / 32;
    const int* src = ei;
    const int* dstp = ei + E;

    float *h, *stats, *t1, *t2, *adv, *awt;
    int* deg;
    cudaGetSymbolAddress((void**)&h, g_h);
    cudaGetSymbolAddress((void**)&stats, g_stats);
    cudaGetSymbolAddress((void**)&t1, g_t1);
    cudaGetSymbolAddress((void**)&t2, g_t2);
    cudaGetSymbolAddress((void**)&adv, g_adv);
    cudaGetSymbolAddress((void**)&awt, g_awt);
    cudaGetSymbolAddress((void**)&deg, g_deg);

    const int TPB = 256;
    int nblocks = N / TPB;              // 512
    int eblocks = (E + TPB - 1) / TPB;

    prep_kernel<<<64, 256>>>(c1W1, c2W1, c3W1, aW);

    // CSR build (once; reused by all 3 convs)
    cudaMemsetAsync(deg, 0, (size_t)N * sizeof(int), 0);
    deg_kernel<<<eblocks, TPB>>>(dstp, E);
    blocksum_kernel<<<nblocks, TPB>>>();
    scanblocks_kernel<<<1, NBLK>>>(nblocks);
    rowptr_kernel<<<nblocks, TPB>>>();
    fill_kernel<<<eblocks, TPB>>>(src, dstp, E);

    prep1_kernel<<<nblocks, TPB>>>(x, c1b1, N);

    const float* W2s[3] = {c1W2, c2W2, c3W2};
    const float* b2s[3] = {c1b2, c2b2, c3b2};
    const float* b1next[3] = {c2b1, c3b1, c3b1};

    for (int c = 0; c < 3; c++) {
        cudaMemsetAsync(stats, 0, 64 * sizeof(float), 0);
        csr_conv_kernel<<<N / 64, TPB>>>(W2s[c], b2s[c], N);
        if (c < 2)
            bn_prep_kernel<false><<<nblocks, TPB>>>(bn_g + c * 32, bn_b + c * 32,
                                                    b1next[c], c + 1, N);
        else
            bn_prep_kernel<true><<<nblocks, TPB>>>(bn_g + 64, bn_b + 64, c3b1, 0, N);
    }

    // ---- dense head: g_h is [B, 1024] row-major ----
    dim3 g1(256 / 64, B / 64);
    gemm_bias_kernel<true><<<g1, 256>>>(h, mW1, mb1, t1, B, 256, 1024);
    gemm_bias_kernel<true><<<g1, 256>>>(t1, mW2, mb2, t2, B, 256, 256);
    gemm_bias_kernel<true><<<g1, 256>>>(t2, mW3, mb3, t1, B, 256, 256);

    value_kernel<<<64, 256>>>(t1, vW, vb, B);
    dim3 g2(1, B / 64);
    gemm_bias_kernel<false><<<g2, 256>>>(t1, awt, ab, adv, B, 64, 256);
    q_kernel<<<(B * 64 + 255) / 256, 256>>>((float*)d_out, B);
}

// round 5
// speedup vs baseline: 2.1785x; 1.4366x over previous
#include <cuda_runtime.h>

// ---------------------------------------------------------------------------
// Shapes fixed by the dataset: N=131072 nodes, S=32, E=2M edges, B=4096
// ---------------------------------------------------------------------------
#define MAXN 131072
#define MAXE (2 * 1024 * 1024)
#define MAXB 4096
#define NBLK 512                      // N / 256

// Scratch (static device globals)
__device__ float g_pij[MAXN * 32];    // per-node [pi(16)+b1 | pj(16)]
__device__ float g_hacc[MAXN * 32];   // conv output (pre-BN)
__device__ float g_h[MAXN * 32];      // final activations (dense input)
__device__ int   g_deg[MAXN];         // in-degree per node
__device__ int   g_rowptr[MAXN];      // CSR row start
__device__ int   g_cursor[MAXN];      // fill cursors
__device__ int   g_col[MAXE];         // src ids grouped by dst
__device__ int   g_bsums[NBLK];       // scan scratch
__device__ float g_stats[64];         // per-channel sum / sumsq
__device__ float g_t1[MAXB * 256];
__device__ float g_t2[MAXB * 256];
__device__ float g_val[MAXB];
__device__ float g_adv[MAXB * 64];

// ---------------------------------------------------------------------------
// CSR build: degree -> fused chunk-sum + scan -> per-chunk rowptr -> fill
// ---------------------------------------------------------------------------
__global__ void deg_kernel(const int* __restrict__ dst, int E) {
    int e = blockIdx.x * blockDim.x + threadIdx.x;
    if (e < E) atomicAdd(&g_deg[dst[e]], 1);
}

// 1 block, NBLK threads: thread t sums its 256-node chunk, then exclusive scan
__global__ void bscan_kernel(int nb) {
    __shared__ int sh[NBLK];
    int t = threadIdx.x;
    int s = 0;
    if (t < nb) {
        const int4* p = reinterpret_cast<const int4*>(g_deg + t * 256);
#pragma unroll 8
        for (int i = 0; i < 64; i++) {
            int4 v = p[i];
            s += v.x + v.y + v.z + v.w;
        }
    }
    sh[t] = s;
    __syncthreads();
    for (int o = 1; o < NBLK; o <<= 1) {
        int v = (t >= o) ? sh[t - o] : 0;
        __syncthreads();
        sh[t] += v;
        __syncthreads();
    }
    g_bsums[t] = (t == 0) ? 0 : sh[t - 1];  // exclusive
}

__global__ void rowptr_kernel() {  // grid NBLK, block 256
    __shared__ int sh[256];
    int t = threadIdx.x;
    int n = blockIdx.x * 256 + t;
    int d = g_deg[n];
    sh[t] = d;
    __syncthreads();
    for (int o = 1; o < 256; o <<= 1) {
        int v = (t >= o) ? sh[t - o] : 0;
        __syncthreads();
        sh[t] += v;
        __syncthreads();
    }
    int start = g_bsums[blockIdx.x] + sh[t] - d;
    g_rowptr[n] = start;
    g_cursor[n] = start;
}

__global__ void fill_kernel(const int* __restrict__ src,
                            const int* __restrict__ dst, int E) {
    int e = blockIdx.x * blockDim.x + threadIdx.x;
    if (e < E) {
        int p = atomicAdd(&g_cursor[dst[e]], 1);
        g_col[p] = src[e];
    }
}

// ---------------------------------------------------------------------------
// conv1 pi/pj from raw x (F=2); weights folded inline; b1 folded into pi
// ---------------------------------------------------------------------------
__global__ void prep1_kernel(const float* __restrict__ x,
                             const float* __restrict__ W1,
                             const float* __restrict__ b1v, int N) {
    __shared__ float sWd[32], sWb[32], sB1[16];
    if (threadIdx.x < 32) {
        sWd[threadIdx.x] = W1[threadIdx.x] - W1[32 + threadIdx.x];
        sWb[threadIdx.x] = W1[32 + threadIdx.x];
    }
    if (threadIdx.x < 16) sB1[threadIdx.x] = b1v[threadIdx.x];
    __syncthreads();
    int n = blockIdx.x * blockDim.x + threadIdx.x;
    if (n >= N) return;
    float2 xv = reinterpret_cast<const float2*>(x)[n];
    float out[32];
#pragma unroll
    for (int j = 0; j < 16; j++) {
        out[j]      = sB1[j] + fmaf(xv.x, sWd[j], xv.y * sWd[16 + j]);
        out[16 + j] = fmaf(xv.x, sWb[j], xv.y * sWb[16 + j]);
    }
    float4* o = reinterpret_cast<float4*>(g_pij + (size_t)n * 32);
#pragma unroll
    for (int q = 0; q < 8; q++)
        o[q] = make_float4(out[q * 4], out[q * 4 + 1], out[q * 4 + 2], out[q * 4 + 3]);
}

// ---------------------------------------------------------------------------
// csr_conv: gather-only conv. 4 lanes per node; gather loop unrolled x4.
//   h16 = Sum_j relu(pi[n] + pj[col[j]])   (register accumulation)
//   o   = h16 @ W2 + deg*b2                (shfl exchange)
//   g_hacc[n] = o ; fused BN stats
// Launch: grid = N/64, block 256.
// ---------------------------------------------------------------------------
__global__ void csr_conv_kernel(const float* __restrict__ W2,
                                const float* __restrict__ b2v, int N) {
    __shared__ float sW2[512];
    __shared__ float sB2[32];
    __shared__ float bsum[32], bsq[32];
    int t = threadIdx.x;
    for (int i = t; i < 512; i += 256) sW2[i] = W2[i];
    if (t < 32) {
        sB2[t] = b2v[t];
        bsum[t] = 0.0f;
        bsq[t] = 0.0f;
    }
    __syncthreads();

    int l = t >> 2;          // node within block (0..63)
    int q = t & 3;           // quarter (0..3)
    int n = blockIdx.x * 64 + l;

    float4 u = *reinterpret_cast<const float4*>(g_pij + (size_t)n * 32 + q * 4);
    int rp = g_rowptr[n];
    int dg = g_deg[n];
    const int* cp = g_col + rp;

    float4 acc = make_float4(0.0f, 0.0f, 0.0f, 0.0f);
    int i = 0;
    int end4 = dg & ~3;
    for (; i < end4; i += 4) {
        int s0 = __ldg(cp + i);
        int s1 = __ldg(cp + i + 1);
        int s2 = __ldg(cp + i + 2);
        int s3 = __ldg(cp + i + 3);
        float4 v0 = *reinterpret_cast<const float4*>(g_pij + (size_t)s0 * 32 + 16 + q * 4);
        float4 v1 = *reinterpret_cast<const float4*>(g_pij + (size_t)s1 * 32 + 16 + q * 4);
        float4 v2 = *reinterpret_cast<const float4*>(g_pij + (size_t)s2 * 32 + 16 + q * 4);
        float4 v3 = *reinterpret_cast<const float4*>(g_pij + (size_t)s3 * 32 + 16 + q * 4);
        acc.x += fmaxf(u.x + v0.x, 0.0f) + fmaxf(u.x + v1.x, 0.0f) +
                 fmaxf(u.x + v2.x, 0.0f) + fmaxf(u.x + v3.x, 0.0f);
        acc.y += fmaxf(u.y + v0.y, 0.0f) + fmaxf(u.y + v1.y, 0.0f) +
                 fmaxf(u.y + v2.y, 0.0f) + fmaxf(u.y + v3.y, 0.0f);
        acc.z += fmaxf(u.z + v0.z, 0.0f) + fmaxf(u.z + v1.z, 0.0f) +
                 fmaxf(u.z + v2.z, 0.0f) + fmaxf(u.z + v3.z, 0.0f);
        acc.w += fmaxf(u.w + v0.w, 0.0f) + fmaxf(u.w + v1.w, 0.0f) +
                 fmaxf(u.w + v2.w, 0.0f) + fmaxf(u.w + v3.w, 0.0f);
    }
    for (; i < dg; i++) {
        int s = __ldg(cp + i);
        float4 v = *reinterpret_cast<const float4*>(g_pij + (size_t)s * 32 + 16 + q * 4);
        acc.x += fmaxf(u.x + v.x, 0.0f);
        acc.y += fmaxf(u.y + v.y, 0.0f);
        acc.z += fmaxf(u.z + v.z, 0.0f);
        acc.w += fmaxf(u.w + v.w, 0.0f);
    }

    // exchange quarters within the 4-lane node group -> full h[16] per lane
    int lanebase = (t & 31) & ~3;
    float h[16];
#pragma unroll
    for (int k = 0; k < 16; k++) {
        float comp = (k & 3) == 0 ? acc.x : (k & 3) == 1 ? acc.y
                   : (k & 3) == 2 ? acc.z : acc.w;
        h[k] = __shfl_sync(0xffffffffu, comp, lanebase | (k >> 2), 32);
    }

    // o[8] for output channels j0..j0+7
    int j0 = q * 8;
    float dgf = (float)dg;
    float o[8];
#pragma unroll
    for (int j = 0; j < 8; j++) o[j] = dgf * sB2[j0 + j];
#pragma unroll
    for (int k = 0; k < 16; k++) {
        float hv = h[k];
#pragma unroll
        for (int j = 0; j < 8; j++) o[j] = fmaf(hv, sW2[k * 32 + j0 + j], o[j]);
    }
    float4* op = reinterpret_cast<float4*>(g_hacc + (size_t)n * 32 + j0);
    op[0] = make_float4(o[0], o[1], o[2], o[3]);
    op[1] = make_float4(o[4], o[5], o[6], o[7]);

    // BN stats: butterfly over the 8 nodes of this warp (lane strides 4,8,16)
#pragma unroll
    for (int j = 0; j < 8; j++) {
        float v = o[j];
        float v2 = v * v;
#pragma unroll
        for (int off = 4; off < 32; off <<= 1) {
            v += __shfl_xor_sync(0xffffffffu, v, off);
            v2 += __shfl_xor_sync(0xffffffffu, v2, off);
        }
        if ((t & 31) < 4) {
            atomicAdd(&bsum[j0 + j], v);
            atomicAdd(&bsq[j0 + j], v2);
        }
    }
    __syncthreads();
    if (t < 32)
        atomicAdd(&g_stats[t], bsum[t]);
    else if (t < 64)
        atomicAdd(&g_stats[t], bsq[t - 32]);
}

// ---------------------------------------------------------------------------
// BN apply + ReLU, fused with next conv's pi/pj precompute (or final write).
// Next conv's folded weights computed inline from raw W1; b1 folded into pi.
// ---------------------------------------------------------------------------
template <bool FINAL>
__global__ void bn_prep_kernel(const float* __restrict__ gamma,
                               const float* __restrict__ beta,
                               const float* __restrict__ W1next,
                               const float* __restrict__ b1next, int N) {
    __shared__ float sc[32], sh[32];
    __shared__ float sWd[512], sWb[512], sB1[16];
    if (threadIdx.x < 32) {
        int c = threadIdx.x;
        float invn = 1.0f / (float)N;
        float mu = g_stats[c] * invn;
        float var = g_stats[32 + c] * invn - mu * mu;
        float s = rsqrtf(var + 1e-5f) * gamma[c];
        sc[c] = s;
        sh[c] = beta[c] - mu * s;
    }
    if (!FINAL) {
        for (int i = threadIdx.x; i < 512; i += blockDim.x) {
            float wb = W1next[512 + i];
            sWd[i] = W1next[i] - wb;
            sWb[i] = wb;
        }
        if (threadIdx.x >= 32 && threadIdx.x < 48)
            sB1[threadIdx.x - 32] = b1next[threadIdx.x - 32];
    }
    __syncthreads();
    int n = blockIdx.x * blockDim.x + threadIdx.x;
    if (n >= N) return;

    float hn[32];
    const float4* ip = reinterpret_cast<const float4*>(g_hacc + (size_t)n * 32);
#pragma unroll
    for (int qq = 0; qq < 8; qq++) {
        float4 v = ip[qq];
        hn[qq * 4 + 0] = fmaxf(fmaf(v.x, sc[qq * 4 + 0], sh[qq * 4 + 0]), 0.0f);
        hn[qq * 4 + 1] = fmaxf(fmaf(v.y, sc[qq * 4 + 1], sh[qq * 4 + 1]), 0.0f);
        hn[qq * 4 + 2] = fmaxf(fmaf(v.z, sc[qq * 4 + 2], sh[qq * 4 + 2]), 0.0f);
        hn[qq * 4 + 3] = fmaxf(fmaf(v.w, sc[qq * 4 + 3], sh[qq * 4 + 3]), 0.0f);
    }
    if (FINAL) {
        float4* op = reinterpret_cast<float4*>(g_h + (size_t)n * 32);
#pragma unroll
        for (int qq = 0; qq < 8; qq++)
            op[qq] = make_float4(hn[qq * 4], hn[qq * 4 + 1], hn[qq * 4 + 2], hn[qq * 4 + 3]);
    } else {
        float pi[16], pj[16];
#pragma unroll
        for (int j = 0; j < 16; j++) { pi[j] = sB1[j]; pj[j] = 0.0f; }
#pragma unroll
        for (int k = 0; k < 32; k++) {
            float v = hn[k];
#pragma unroll
            for (int j = 0; j < 16; j++) {
                pi[j] = fmaf(v, sWd[k * 16 + j], pi[j]);
                pj[j] = fmaf(v, sWb[k * 16 + j], pj[j]);
            }
        }
        float4* op = reinterpret_cast<float4*>(g_pij + (size_t)n * 32);
#pragma unroll
        for (int qq = 0; qq < 4; qq++) {
            op[qq] = make_float4(pi[qq * 4], pi[qq * 4 + 1], pi[qq * 4 + 2], pi[qq * 4 + 3]);
            op[4 + qq] = make_float4(pj[qq * 4], pj[qq * 4 + 1], pj[qq * 4 + 2], pj[qq * 4 + 3]);
        }
    }
}

// ---------------------------------------------------------------------------
// Tiled fp32 GEMM: C[M,N] = act(A @ B + bias)
// 128x64 block tile, BK=16, 256 threads, 8x4 micro-tile.
// AWMODE: B element (k,c) = aW[(c>>1)*512 + k*2 + (c&1)] (adv head remap)
// ---------------------------------------------------------------------------
template <bool RELU, bool AWMODE>
__global__ void gemm128_kernel(const float* __restrict__ A,
                               const float* __restrict__ Bm,
                               const float* __restrict__ bias,
                               float* __restrict__ C, int M, int N, int K) {
    const int BM = 128, BN = 64, BK = 16;
    __shared__ float As[BK][BM + 4];
    __shared__ float Bs[BK][BN];
    int tid = threadIdx.x;
    int tx = tid & 15;
    int ty = tid >> 4;
    int bm = blockIdx.y * BM;
    int bn = blockIdx.x * BN;

    float acc[8][4];
#pragma unroll
    for (int u = 0; u < 8; u++)
#pragma unroll
        for (int v = 0; v < 4; v++) acc[u][v] = 0.0f;

    for (int k0 = 0; k0 < K; k0 += BK) {
        // A tile: 128x16 = 512 float4, 2 per thread, transpose into As[k][m]
#pragma unroll
        for (int qq = 0; qq < 2; qq++) {
            int i = tid + qq * 256;
            int r = i >> 2;
            int c4 = (i & 3) * 4;
            float4 v = *reinterpret_cast<const float4*>(
                A + (size_t)(bm + r) * K + k0 + c4);
            As[c4 + 0][r] = v.x;
            As[c4 + 1][r] = v.y;
            As[c4 + 2][r] = v.z;
            As[c4 + 3][r] = v.w;
        }
        // B tile
        if (!AWMODE) {
            int r = tid >> 4;
            int c4 = (tid & 15) * 4;
            *reinterpret_cast<float4*>(&Bs[r][c4]) =
                *reinterpret_cast<const float4*>(Bm + (size_t)(k0 + r) * N + bn + c4);
        } else {
#pragma unroll
            for (int qq = 0; qq < 4; qq++) {
                int i = tid + qq * 256;
                int r = i >> 6, c = i & 63;
                int gc = bn + c;
                Bs[r][c] = Bm[(gc >> 1) * 512 + (k0 + r) * 2 + (gc & 1)];
            }
        }
        __syncthreads();
#pragma unroll
        for (int k = 0; k < BK; k++) {
            float4 b = *reinterpret_cast<const float4*>(&Bs[k][tx * 4]);
            float4 a0 = *reinterpret_cast<const float4*>(&As[k][ty * 8]);
            float4 a1 = *reinterpret_cast<const float4*>(&As[k][ty * 8 + 4]);
            float av[8] = {a0.x, a0.y, a0.z, a0.w, a1.x, a1.y, a1.z, a1.w};
            float bv[4] = {b.x, b.y, b.z, b.w};
#pragma unroll
            for (int u = 0; u < 8; u++)
#pragma unroll
                for (int v = 0; v < 4; v++)
                    acc[u][v] = fmaf(av[u], bv[v], acc[u][v]);
        }
        __syncthreads();
    }
    float4 bb = *reinterpret_cast<const float4*>(bias + bn + tx * 4);
#pragma unroll
    for (int u = 0; u < 8; u++) {
        int row = bm + ty * 8 + u;
        float4 r;
        r.x = acc[u][0] + bb.x;
        r.y = acc[u][1] + bb.y;
        r.z = acc[u][2] + bb.z;
        r.w = acc[u][3] + bb.w;
        if (RELU) {
            r.x = fmaxf(r.x, 0.0f);
            r.y = fmaxf(r.y, 0.0f);
            r.z = fmaxf(r.z, 0.0f);
            r.w = fmaxf(r.w, 0.0f);
        }
        *reinterpret_cast<float4*>(C + (size_t)row * N + bn + tx * 4) = r;
    }
}

__global__ void value_kernel(const float* __restrict__ X,
                             const float* __restrict__ vW,
                             const float* __restrict__ vb, int B) {
    int gwarp = (blockIdx.x * blockDim.x + threadIdx.x) >> 5;
    int lane = threadIdx.x & 31;
    int nwarps = (gridDim.x * blockDim.x) >> 5;
    for (int b = gwarp; b < B; b += nwarps) {
        const float* row = X + (size_t)b * 256;
        float s = 0.0f;
#pragma unroll
        for (int f = lane; f < 256; f += 32) s = fmaf(row[f], vW[f], s);
#pragma unroll
        for (int o = 16; o; o >>= 1) s += __shfl_xor_sync(0xffffffffu, s, o);
        if (lane == 0) g_val[b] = s + vb[0];
    }
}

__global__ void q_kernel(float* __restrict__ q, int B) {
    int i = blockIdx.x * blockDim.x + threadIdx.x;
    if (i >= B * 64) return;
    int b = i >> 6;
    float a0 = g_adv[i];
    float a1 = g_adv[i ^ 1];
    q[i] = g_val[b] + 0.5f * (a0 - a1);
}

// ---------------------------------------------------------------------------
extern "C" void kernel_launch(void* const* d_in, const int* in_sizes, int n_in,
                              void* d_out, int out_size) {
    const float* x    = (const float*)d_in[0];
    const int*   ei   = (const int*)d_in[1];
    const float* c1W1 = (const float*)d_in[2];
    const float* c1b1 = (const float*)d_in[3];
    const float* c1W2 = (const float*)d_in[4];
    const float* c1b2 = (const float*)d_in[5];
    const float* c2W1 = (const float*)d_in[6];
    const float* c2b1 = (const float*)d_in[7];
    const float* c2W2 = (const float*)d_in[8];
    const float* c2b2 = (const float*)d_in[9];
    const float* c3W1 = (const float*)d_in[10];
    const float* c3b1 = (const float*)d_in[11];
    const float* c3W2 = (const float*)d_in[12];
    const float* c3b2 = (const float*)d_in[13];
    const float* bn_g = (const float*)d_in[14];
    const float* bn_b = (const float*)d_in[15];
    const float* mW1  = (const float*)d_in[16];
    const float* mb1  = (const float*)d_in[17];
    const float* mW2  = (const float*)d_in[18];
    const float* mb2  = (const float*)d_in[19];
    const float* mW3  = (const float*)d_in[20];
    const float* mb3  = (const float*)d_in[21];
    const float* vW   = (const float*)d_in[22];
    const float* vb   = (const float*)d_in[23];
    const float* aW   = (const float*)d_in[24];
    const float* ab   = (const float*)d_in[25];

    int N = in_sizes[0] / 2;
    int E = in_sizes[1] / 2;
    int B = N / 32;
    const int* src = ei;
    const int* dstp = ei + E;

    float *h, *stats, *t1, *t2, *adv;
    int* deg;
    cudaGetSymbolAddress((void**)&h, g_h);
    cudaGetSymbolAddress((void**)&stats, g_stats);
    cudaGetSymbolAddress((void**)&t1, g_t1);
    cudaGetSymbolAddress((void**)&t2, g_t2);
    cudaGetSymbolAddress((void**)&adv, g_adv);
    cudaGetSymbolAddress((void**)&deg, g_deg);

    const int TPB = 256;
    int nblocks = N / TPB;              // 512
    int eblocks = (E + TPB - 1) / TPB;

    // CSR build (once; reused by all 3 convs)
    cudaMemsetAsync(deg, 0, (size_t)N * sizeof(int), 0);
    prep1_kernel<<<nblocks, TPB>>>(x, c1W1, c1b1, N);
    deg_kernel<<<eblocks, TPB>>>(dstp, E);
    bscan_kernel<<<1, NBLK>>>(nblocks);
    rowptr_kernel<<<nblocks, TPB>>>();
    fill_kernel<<<eblocks, TPB>>>(src, dstp, E);

    const float* W2s[3] = {c1W2, c2W2, c3W2};
    const float* b2s[3] = {c1b2, c2b2, c3b2};
    const float* W1next[3] = {c2W1, c3W1, c3W1};
    const float* b1next[3] = {c2b1, c3b1, c3b1};

    for (int c = 0; c < 3; c++) {
        cudaMemsetAsync(stats, 0, 64 * sizeof(float), 0);
        csr_conv_kernel<<<N / 64, TPB>>>(W2s[c], b2s[c], N);
        if (c < 2)
            bn_prep_kernel<false><<<nblocks, TPB>>>(bn_g + c * 32, bn_b + c * 32,
                                                    W1next[c], b1next[c], N);
        else
            bn_prep_kernel<true><<<nblocks, TPB>>>(bn_g + 64, bn_b + 64, c3W1,
                                                   c3b1, N);
    }

    // ---- dense head: g_h is [B, 1024] row-major ----
    dim3 g1(256 / 64, B / 128);
    gemm128_kernel<true, false><<<g1, 256>>>(h, mW1, mb1, t1, B, 256, 1024);
    gemm128_kernel<true, false><<<g1, 256>>>(t1, mW2, mb2, t2, B, 256, 256);
    gemm128_kernel<true, false><<<g1, 256>>>(t2, mW3, mb3, t1, B, 256, 256);

    value_kernel<<<64, 256>>>(t1, vW, vb, B);
    dim3 g2(1, B / 128);
    gemm128_kernel<false, true><<<g2, 256>>>(t1, aW, ab, adv, B, 64, 256);
    q_kernel<<<(B * 64 + 255) / 256, 256>>>((float*)d_out, B);
}